// round 9
// baseline (speedup 1.0000x reference)
#include <cuda_runtime.h>
#include <cuda.h>
#include <cuda_fp8.h>
#include <cstdint>

// ============================================================================
// Problem dims (fixed by the dataset)
// ============================================================================
#define MDIM 4096
#define KDIM 4096
#define NDIM 16384

// GEMM tiling (fp8 operands): 4 CTAs/SM x 128 threads -> 8 warps/SMSP
#define BM 64
#define BN 128
#define BK 128                 // fp8 elements per k-chunk (128B rows)
#define KCHUNKS (KDIM / BK)    // 32
#define STAGES 2
#define ROWB 144               // 128 data + 16 pad -> conflict-free ldmatrix
#define STAGE_BYTES ((BM + BN) * ROWB)       // 27648
#define SMEM_TOTAL (STAGES * STAGE_BYTES)    // 55296 (x4 CTAs = 221KB/SM)

// CTA swizzle: supertile of 8 N-blocks x 64 M-blocks (512 CTAs)
#define SUPER_N 8
#define MBLK (MDIM / BM)       // 64
#define NBLK (NDIM / BN)       // 128

// Scratch (allocation-free rule: __device__ globals)
__device__ __align__(1024) uint8_t g_xq[(size_t)MDIM * KDIM];
__device__ __align__(1024) uint8_t g_wq[(size_t)NDIM * KDIM];
__device__ float g_xs[MDIM];

// ============================================================================
// PTX helpers (family-portable only: cp.async, ldmatrix, mma.sync)
// ============================================================================
__device__ __forceinline__ uint32_t smem_u32(const void* p) {
    uint32_t a;
    asm("{ .reg .u64 t; cvta.to.shared.u64 t, %1; cvt.u32.u64 %0, t; }"
        : "=r"(a) : "l"(p));
    return a;
}
__device__ __forceinline__ void cp16(uint32_t dst, const void* src) {
    asm volatile("cp.async.cg.shared.global [%0], [%1], 16;"
                 :: "r"(dst), "l"(src));
}
__device__ __forceinline__ void cp_commit() {
    asm volatile("cp.async.commit_group;");
}
#define LDSM_X4(r0, r1, r2, r3, addr)                                         \
    asm volatile("ldmatrix.sync.aligned.m8n8.x4.shared.b16 {%0,%1,%2,%3}, [%4];" \
                 : "=r"(r0), "=r"(r1), "=r"(r2), "=r"(r3) : "r"(addr))

__device__ __forceinline__ void mma_fp8(float* d, const uint32_t* a,
                                        uint32_t b0, uint32_t b1) {
    asm volatile(
        "mma.sync.aligned.m16n8k32.row.col.f32.e4m3.e4m3.f32 "
        "{%0,%1,%2,%3}, {%4,%5,%6,%7}, {%8,%9}, {%0,%1,%2,%3};"
        : "+f"(d[0]), "+f"(d[1]), "+f"(d[2]), "+f"(d[3])
        : "r"(a[0]), "r"(a[1]), "r"(a[2]), "r"(a[3]), "r"(b0), "r"(b1));
}

// ============================================================================
// Kernel 1: per-token dynamic quantization of x (matches reference rounding)
// ============================================================================
__global__ void __launch_bounds__(256) quant_x_kernel(const float* __restrict__ x,
                                                      uint8_t* __restrict__ xq,
                                                      float* __restrict__ xs) {
    const int row = blockIdx.x;
    const float4* xr = reinterpret_cast<const float4*>(x + (size_t)row * KDIM);
    uint32_t* qr = reinterpret_cast<uint32_t*>(xq + (size_t)row * KDIM);
    const int t = threadIdx.x;

    float4 v[4];
    float amax = 0.0f;
#pragma unroll
    for (int i = 0; i < 4; i++) {
        v[i] = __ldcs(xr + t + 256 * i);   // single-pass read, keep L2 clean
        amax = fmaxf(amax, fmaxf(fmaxf(fabsf(v[i].x), fabsf(v[i].y)),
                                 fmaxf(fabsf(v[i].z), fabsf(v[i].w))));
    }
#pragma unroll
    for (int o = 16; o; o >>= 1) amax = fmaxf(amax, __shfl_xor_sync(~0u, amax, o));

    __shared__ float warpmax[8];
    __shared__ float sscale;
    if ((t & 31) == 0) warpmax[t >> 5] = amax;
    __syncthreads();
    if (t < 32) {
        float a = (t < 8) ? warpmax[t] : 0.0f;
#pragma unroll
        for (int o = 4; o; o >>= 1) a = fmaxf(a, __shfl_xor_sync(~0u, a, o));
        if (t == 0) sscale = fmaxf(__fdiv_rn(a, 448.0f), 1e-12f);
    }
    __syncthreads();
    const float scale = sscale;

#pragma unroll
    for (int i = 0; i < 4; i++) {
        uint32_t p =
            (uint32_t)__nv_cvt_float_to_fp8(__fdiv_rn(v[i].x, scale), __NV_SATFINITE, __NV_E4M3)
          | ((uint32_t)__nv_cvt_float_to_fp8(__fdiv_rn(v[i].y, scale), __NV_SATFINITE, __NV_E4M3) << 8)
          | ((uint32_t)__nv_cvt_float_to_fp8(__fdiv_rn(v[i].z, scale), __NV_SATFINITE, __NV_E4M3) << 16)
          | ((uint32_t)__nv_cvt_float_to_fp8(__fdiv_rn(v[i].w, scale), __NV_SATFINITE, __NV_E4M3) << 24);
        qr[t + 256 * i] = p;
    }
    if (t == 0) xs[row] = scale;
}

// ============================================================================
// Kernel 2: weight fp32 (values already on fp8 grid) -> fp8 codes (exact)
// ============================================================================
__global__ void __launch_bounds__(256) quant_w_kernel(const float* __restrict__ w,
                                                      uint8_t* __restrict__ wq) {
    const size_t i = (size_t)blockIdx.x * 256 + threadIdx.x;   // float4 index
    float4 v = __ldcs(reinterpret_cast<const float4*>(w) + i); // single-pass read
    uint32_t p =
        (uint32_t)__nv_cvt_float_to_fp8(v.x, __NV_SATFINITE, __NV_E4M3)
      | ((uint32_t)__nv_cvt_float_to_fp8(v.y, __NV_SATFINITE, __NV_E4M3) << 8)
      | ((uint32_t)__nv_cvt_float_to_fp8(v.z, __NV_SATFINITE, __NV_E4M3) << 16)
      | ((uint32_t)__nv_cvt_float_to_fp8(v.w, __NV_SATFINITE, __NV_E4M3) << 24);
    reinterpret_cast<uint32_t*>(wq)[i] = p;
}

// ============================================================================
// Kernel 3: fp8 GEMM via mma.sync m16n8k32, cp.async 2-stage, 4 CTAs/SM,
// 128 threads (4 warps, 2M x 2N, warp tile 32x64). Tile 64x128.
// Refill cp.async interleaved into the mma groups (LSU burst smoothing).
// ============================================================================
__global__ void __launch_bounds__(128, 4) fp8_gemm_kernel(
    const uint8_t* __restrict__ xq,
    const uint8_t* __restrict__ wq,
    const float* __restrict__ xs,
    const float* __restrict__ ws,
    const float* __restrict__ bias,
    float* __restrict__ out)
{
    extern __shared__ char smem[];
    const uint32_t sb = smem_u32(smem);
    const int tid  = threadIdx.x;
    const int wid  = tid >> 5;
    const int lane = tid & 31;

    // Supertile swizzle: 512-CTA groups of SUPER_N n-blocks x 64 m-blocks
    const int bid    = blockIdx.x;
    const int sid    = bid / (SUPER_N * MBLK);
    const int within = bid % (SUPER_N * MBLK);
    const int n0 = (sid * SUPER_N + (within % SUPER_N)) * BN;
    const int m0 = (within / SUPER_N) * BM;

    const int mbase = (wid & 1) * 32;   // warp M offset in tile
    const int nbase = (wid >> 1) * 64;  // warp N offset in tile

    float acc[2][8][4];
#pragma unroll
    for (int a = 0; a < 2; a++)
#pragma unroll
        for (int b = 0; b < 8; b++)
#pragma unroll
            for (int c = 0; c < 4; c++) acc[a][b][c] = 0.0f;

    // Producer mapping: 192 rows x 128B per stage = 1536 segs, 12/thread.
    const int r0  = tid >> 3;      // 0..15 (rows step by 16)
    const int seg = tid & 7;       // 0..7
    const uint8_t* pA = xq + (size_t)(m0 + r0) * KDIM + seg * 16;
    const uint8_t* pB = wq + (size_t)(n0 + r0) * KDIM + seg * 16;
    const uint32_t sA = sb + (uint32_t)r0 * ROWB + seg * 16;
    const uint32_t sB = sb + BM * ROWB + (uint32_t)r0 * ROWB + seg * 16;
    const size_t gp16 = (size_t)16 * KDIM;   // 16 rows in bytes

    // ldmatrix per-thread addresses (stage-base relative)
    const uint32_t a_off = (uint32_t)(mbase + ((lane >> 3) & 1) * 8 + (lane & 7)) * ROWB
                         + (lane >> 4) * 16;
    const uint32_t b_off = (uint32_t)(BM * ROWB)
                         + (uint32_t)(nbase + (lane >> 4) * 8 + (lane & 7)) * ROWB
                         + ((lane >> 3) & 1) * 16;

    // Prologue: chunk 0 -> stage 0
#pragma unroll
    for (int j = 0; j < 4; j++)
        cp16(sA + (uint32_t)j * 16 * ROWB, pA + j * gp16);
#pragma unroll
    for (int j = 0; j < 8; j++)
        cp16(sB + (uint32_t)j * 16 * ROWB, pB + j * gp16);
    cp_commit();

    for (int kc = 0; kc < KCHUNKS; kc++) {
        asm volatile("cp.async.wait_group 0;");   // copies of chunk kc done
        __syncthreads();                          // visible to all; prior compute done

        const bool refill = (kc + 1 < KCHUNKS);
        const uint32_t so  = (uint32_t)((kc + 1) & 1) * STAGE_BYTES;
        const size_t   go  = (size_t)(kc + 1) * BK;
        const uint32_t st  = sb + (uint32_t)(kc & 1) * STAGE_BYTES;

#pragma unroll
        for (int kst = 0; kst < 4; kst++) {       // 4 x k32
            uint32_t af[2][4], bf[4][4];
#pragma unroll
            for (int mj = 0; mj < 2; mj++) {
                LDSM_X4(af[mj][0], af[mj][1], af[mj][2], af[mj][3],
                        st + a_off + (uint32_t)mj * 16 * ROWB + kst * 32);
            }
#pragma unroll
            for (int g = 0; g < 4; g++) {
                LDSM_X4(bf[g][0], bf[g][1], bf[g][2], bf[g][3],
                        st + b_off + (uint32_t)g * 16 * ROWB + kst * 32);
            }

            // Interleaved refill: 4 cp16 per kst group (0..2), commit at 2.
            if (refill) {
                if (kst == 0) {
#pragma unroll
                    for (int j = 0; j < 4; j++)
                        cp16(sA + so + (uint32_t)j * 16 * ROWB, pA + go + j * gp16);
                } else if (kst == 1) {
#pragma unroll
                    for (int j = 0; j < 4; j++)
                        cp16(sB + so + (uint32_t)j * 16 * ROWB, pB + go + j * gp16);
                } else if (kst == 2) {
#pragma unroll
                    for (int j = 4; j < 8; j++)
                        cp16(sB + so + (uint32_t)j * 16 * ROWB, pB + go + j * gp16);
                    cp_commit();
                }
            }

#pragma unroll
            for (int mj = 0; mj < 2; mj++)
#pragma unroll
                for (int o = 0; o < 8; o++)
                    mma_fp8(acc[mj][o], af[mj],
                            bf[o >> 1][(o & 1) * 2], bf[o >> 1][(o & 1) * 2 + 1]);
        }
    }

    // ---- Epilogue: fused dequant + bias, streaming float2 stores ----
#pragma unroll
    for (int o = 0; o < 8; o++) {
        const int c = n0 + nbase + o * 8 + 2 * (lane & 3);
        const float ws0 = __ldg(ws + c),   ws1 = __ldg(ws + c + 1);
        const float bi0 = __ldg(bias + c), bi1 = __ldg(bias + c + 1);
#pragma unroll
        for (int mj = 0; mj < 2; mj++) {
            const int r = m0 + mbase + mj * 16 + (lane >> 2);
            const float xs0 = __ldg(xs + r), xs1 = __ldg(xs + r + 8);
            float2 v0, v1;
            v0.x = acc[mj][o][0] * xs0 * ws0 + bi0;
            v0.y = acc[mj][o][1] * xs0 * ws1 + bi1;
            v1.x = acc[mj][o][2] * xs1 * ws0 + bi0;
            v1.y = acc[mj][o][3] * xs1 * ws1 + bi1;
            __stcs(reinterpret_cast<float2*>(out + (size_t)r * NDIM + c), v0);
            __stcs(reinterpret_cast<float2*>(out + (size_t)(r + 8) * NDIM + c), v1);
        }
    }
}

// ============================================================================
// Host
// ============================================================================
extern "C" void kernel_launch(void* const* d_in, const int* in_sizes, int n_in,
                              void* d_out, int out_size) {
    const float* x    = (const float*)d_in[0];
    const float* w    = (const float*)d_in[1];
    const float* ws   = (const float*)d_in[2];
    const float* bias = (const float*)d_in[3];
    float* out = (float*)d_out;

    void *xq_p = nullptr, *wq_p = nullptr, *xs_p = nullptr;
    cudaGetSymbolAddress(&xq_p, g_xq);
    cudaGetSymbolAddress(&wq_p, g_wq);
    cudaGetSymbolAddress(&xs_p, g_xs);

    cudaFuncSetAttribute(fp8_gemm_kernel,
                         cudaFuncAttributeMaxDynamicSharedMemorySize, SMEM_TOTAL);

    quant_x_kernel<<<MDIM, 256>>>(x, (uint8_t*)xq_p, (float*)xs_p);
    quant_w_kernel<<<(unsigned)(((size_t)NDIM * KDIM / 4) / 256), 256>>>(w, (uint8_t*)wq_p);

    const unsigned nblocks = NBLK * MBLK;   // 8192
    fp8_gemm_kernel<<<nblocks, 128, SMEM_TOTAL>>>((const uint8_t*)xq_p,
                                                  (const uint8_t*)wq_p,
                                                  (const float*)xs_p, ws, bias, out);
}

// round 11
// speedup vs baseline: 1.0677x; 1.0677x over previous
#include <cuda_runtime.h>
#include <cuda.h>
#include <cuda_fp8.h>
#include <cstdint>

// ============================================================================
// Problem dims (fixed by the dataset)
// ============================================================================
#define MDIM 4096
#define KDIM 4096
#define NDIM 16384

// GEMM tiling (fp8 operands): 4 CTAs/SM x 128 threads -> 8 warps/SMSP
#define BM 64
#define BN 128
#define BK 128                 // fp8 elements per k-chunk (128B rows)
#define KCHUNKS (KDIM / BK)    // 32
#define STAGES 2
#define ROWB 144               // 128 data + 16 pad -> conflict-free ldmatrix
#define STAGE_BYTES ((BM + BN) * ROWB)       // 27648
#define SMEM_TOTAL (STAGES * STAGE_BYTES)    // 55296 (x4 CTAs = 221KB/SM)

// CTA swizzle: supertile of 8 N-blocks x 64 M-blocks (512 CTAs)
#define SUPER_N 8
#define MBLK (MDIM / BM)       // 64
#define NBLK (NDIM / BN)       // 128

// Fused quant grid split
#define QX_BLOCKS MDIM                                   // 4096
#define QW_BLOCKS ((unsigned)(((size_t)NDIM * KDIM / 4) / 256))  // 65536

// Scratch (allocation-free rule: __device__ globals)
__device__ __align__(1024) uint8_t g_xq[(size_t)MDIM * KDIM];
__device__ __align__(1024) uint8_t g_wq[(size_t)NDIM * KDIM];
__device__ float g_xs[MDIM];

// ============================================================================
// PTX helpers (family-portable only: cp.async, ldmatrix, mma.sync)
// ============================================================================
__device__ __forceinline__ uint32_t smem_u32(const void* p) {
    uint32_t a;
    asm("{ .reg .u64 t; cvta.to.shared.u64 t, %1; cvt.u32.u64 %0, t; }"
        : "=r"(a) : "l"(p));
    return a;
}
__device__ __forceinline__ void cp16(uint32_t dst, const void* src) {
    asm volatile("cp.async.cg.shared.global [%0], [%1], 16;"
                 :: "r"(dst), "l"(src));
}
__device__ __forceinline__ void cp_commit() {
    asm volatile("cp.async.commit_group;");
}
#define LDSM_X4(r0, r1, r2, r3, addr)                                         \
    asm volatile("ldmatrix.sync.aligned.m8n8.x4.shared.b16 {%0,%1,%2,%3}, [%4];" \
                 : "=r"(r0), "=r"(r1), "=r"(r2), "=r"(r3) : "r"(addr))

__device__ __forceinline__ void mma_fp8(float* d, const uint32_t* a,
                                        uint32_t b0, uint32_t b1) {
    asm volatile(
        "mma.sync.aligned.m16n8k32.row.col.f32.e4m3.e4m3.f32 "
        "{%0,%1,%2,%3}, {%4,%5,%6,%7}, {%8,%9}, {%0,%1,%2,%3};"
        : "+f"(d[0]), "+f"(d[1]), "+f"(d[2]), "+f"(d[3])
        : "r"(a[0]), "r"(a[1]), "r"(a[2]), "r"(a[3]), "r"(b0), "r"(b1));
}

// ============================================================================
// Fused quant kernel: blocks [0, QX_BLOCKS) quantize x per-token;
// blocks [QX_BLOCKS, QX_BLOCKS+QW_BLOCKS) recode weight fp32 -> fp8 (exact).
// Independent memory-bound sub-workloads co-scheduled in one launch.
// ============================================================================
__global__ void __launch_bounds__(256) fused_quant_kernel(
    const float* __restrict__ x,
    const float* __restrict__ w,
    uint8_t* __restrict__ xq,
    uint8_t* __restrict__ wq,
    float* __restrict__ xs)
{
    const int t = threadIdx.x;

    if (blockIdx.x >= QX_BLOCKS) {
        // ---- weight recode path ----
        const size_t i = (size_t)(blockIdx.x - QX_BLOCKS) * 256 + t;   // float4 idx
        float4 v = __ldcs(reinterpret_cast<const float4*>(w) + i);
        uint32_t p =
            (uint32_t)__nv_cvt_float_to_fp8(v.x, __NV_SATFINITE, __NV_E4M3)
          | ((uint32_t)__nv_cvt_float_to_fp8(v.y, __NV_SATFINITE, __NV_E4M3) << 8)
          | ((uint32_t)__nv_cvt_float_to_fp8(v.z, __NV_SATFINITE, __NV_E4M3) << 16)
          | ((uint32_t)__nv_cvt_float_to_fp8(v.w, __NV_SATFINITE, __NV_E4M3) << 24);
        reinterpret_cast<uint32_t*>(wq)[i] = p;
        return;
    }

    // ---- per-token x quantization path ----
    const int row = blockIdx.x;
    const float4* xr = reinterpret_cast<const float4*>(x + (size_t)row * KDIM);
    uint32_t* qr = reinterpret_cast<uint32_t*>(xq + (size_t)row * KDIM);

    float4 v[4];
    float amax = 0.0f;
#pragma unroll
    for (int i = 0; i < 4; i++) {
        v[i] = xr[t + 256 * i];
        amax = fmaxf(amax, fmaxf(fmaxf(fabsf(v[i].x), fabsf(v[i].y)),
                                 fmaxf(fabsf(v[i].z), fabsf(v[i].w))));
    }
#pragma unroll
    for (int o = 16; o; o >>= 1) amax = fmaxf(amax, __shfl_xor_sync(~0u, amax, o));

    __shared__ float warpmax[8];
    __shared__ float sscale;
    if ((t & 31) == 0) warpmax[t >> 5] = amax;
    __syncthreads();
    if (t < 32) {
        float a = (t < 8) ? warpmax[t] : 0.0f;
#pragma unroll
        for (int o = 4; o; o >>= 1) a = fmaxf(a, __shfl_xor_sync(~0u, a, o));
        if (t == 0) sscale = fmaxf(__fdiv_rn(a, 448.0f), 1e-12f);
    }
    __syncthreads();
    const float scale = sscale;

#pragma unroll
    for (int i = 0; i < 4; i++) {
        uint32_t p =
            (uint32_t)__nv_cvt_float_to_fp8(__fdiv_rn(v[i].x, scale), __NV_SATFINITE, __NV_E4M3)
          | ((uint32_t)__nv_cvt_float_to_fp8(__fdiv_rn(v[i].y, scale), __NV_SATFINITE, __NV_E4M3) << 8)
          | ((uint32_t)__nv_cvt_float_to_fp8(__fdiv_rn(v[i].z, scale), __NV_SATFINITE, __NV_E4M3) << 16)
          | ((uint32_t)__nv_cvt_float_to_fp8(__fdiv_rn(v[i].w, scale), __NV_SATFINITE, __NV_E4M3) << 24);
        qr[t + 256 * i] = p;
    }
    if (t == 0) xs[row] = scale;
}

// ============================================================================
// GEMM: fp8 mma.sync m16n8k32, cp.async 2-stage burst refill, 4 CTAs/SM,
// 128 threads (4 warps, 2M x 2N, warp tile 32x64). Tile 64x128.
// (Byte-for-byte the R8 structure — best measured config at 1400.9us.)
// ============================================================================
__global__ void __launch_bounds__(128, 4) fp8_gemm_kernel(
    const uint8_t* __restrict__ xq,
    const uint8_t* __restrict__ wq,
    const float* __restrict__ xs,
    const float* __restrict__ ws,
    const float* __restrict__ bias,
    float* __restrict__ out)
{
    extern __shared__ char smem[];
    const uint32_t sb = smem_u32(smem);
    const int tid  = threadIdx.x;
    const int wid  = tid >> 5;
    const int lane = tid & 31;

    // Supertile swizzle: 512-CTA groups of SUPER_N n-blocks x 64 m-blocks
    const int bid    = blockIdx.x;
    const int sid    = bid / (SUPER_N * MBLK);
    const int within = bid % (SUPER_N * MBLK);
    const int n0 = (sid * SUPER_N + (within % SUPER_N)) * BN;
    const int m0 = (within / SUPER_N) * BM;

    const int mbase = (wid & 1) * 32;   // warp M offset in tile
    const int nbase = (wid >> 1) * 64;  // warp N offset in tile

    float acc[2][8][4];
#pragma unroll
    for (int a = 0; a < 2; a++)
#pragma unroll
        for (int b = 0; b < 8; b++)
#pragma unroll
            for (int c = 0; c < 4; c++) acc[a][b][c] = 0.0f;

    // Producer mapping: 192 rows x 128B per stage = 1536 segs, 12/thread.
    const int r0  = tid >> 3;      // 0..15 (rows step by 16)
    const int seg = tid & 7;       // 0..7
    const uint8_t* pA = xq + (size_t)(m0 + r0) * KDIM + seg * 16;
    const uint8_t* pB = wq + (size_t)(n0 + r0) * KDIM + seg * 16;
    const uint32_t sA = sb + (uint32_t)r0 * ROWB + seg * 16;
    const uint32_t sB = sb + BM * ROWB + (uint32_t)r0 * ROWB + seg * 16;
    const size_t gp16 = (size_t)16 * KDIM;   // 16 rows in bytes

    // ldmatrix per-thread addresses (stage-base relative)
    const uint32_t a_off = (uint32_t)(mbase + ((lane >> 3) & 1) * 8 + (lane & 7)) * ROWB
                         + (lane >> 4) * 16;
    const uint32_t b_off = (uint32_t)(BM * ROWB)
                         + (uint32_t)(nbase + (lane >> 4) * 8 + (lane & 7)) * ROWB
                         + ((lane >> 3) & 1) * 16;

    // Prologue: chunk 0 -> stage 0
#pragma unroll
    for (int j = 0; j < 4; j++)
        cp16(sA + (uint32_t)j * 16 * ROWB, pA + j * gp16);
#pragma unroll
    for (int j = 0; j < 8; j++)
        cp16(sB + (uint32_t)j * 16 * ROWB, pB + j * gp16);
    cp_commit();

    for (int kc = 0; kc < KCHUNKS; kc++) {
        asm volatile("cp.async.wait_group 0;");   // own copies of chunk kc done
        __syncthreads();                          // all threads' copies visible;
                                                  // prior compute finished
        // Refill: chunk kc+1 -> stage (kc+1)&1 (consumed at iter kc-1)
        if (kc + 1 < KCHUNKS) {
            const uint32_t so = (uint32_t)((kc + 1) & 1) * STAGE_BYTES;
            const size_t   go = (size_t)(kc + 1) * BK;
#pragma unroll
            for (int j = 0; j < 4; j++)
                cp16(sA + so + (uint32_t)j * 16 * ROWB, pA + go + j * gp16);
#pragma unroll
            for (int j = 0; j < 8; j++)
                cp16(sB + so + (uint32_t)j * 16 * ROWB, pB + go + j * gp16);
            cp_commit();
        }

        const uint32_t st = sb + (uint32_t)(kc & 1) * STAGE_BYTES;
#pragma unroll
        for (int kst = 0; kst < 4; kst++) {       // 4 x k32
            uint32_t af[2][4], bf[4][4];
#pragma unroll
            for (int mj = 0; mj < 2; mj++) {
                LDSM_X4(af[mj][0], af[mj][1], af[mj][2], af[mj][3],
                        st + a_off + (uint32_t)mj * 16 * ROWB + kst * 32);
            }
#pragma unroll
            for (int g = 0; g < 4; g++) {
                LDSM_X4(bf[g][0], bf[g][1], bf[g][2], bf[g][3],
                        st + b_off + (uint32_t)g * 16 * ROWB + kst * 32);
            }
#pragma unroll
            for (int mj = 0; mj < 2; mj++)
#pragma unroll
                for (int o = 0; o < 8; o++)
                    mma_fp8(acc[mj][o], af[mj],
                            bf[o >> 1][(o & 1) * 2], bf[o >> 1][(o & 1) * 2 + 1]);
        }
    }

    // ---- Epilogue: fused dequant + bias, streaming float2 stores ----
    const int rbase = m0 + mbase + (lane >> 2);
    const float xsv[2][2] = {
        { __ldg(xs + rbase),      __ldg(xs + rbase + 8)  },
        { __ldg(xs + rbase + 16), __ldg(xs + rbase + 24) }
    };
#pragma unroll
    for (int o = 0; o < 8; o++) {
        const int c = n0 + nbase + o * 8 + 2 * (lane & 3);
        const float ws0 = __ldg(ws + c),   ws1 = __ldg(ws + c + 1);
        const float bi0 = __ldg(bias + c), bi1 = __ldg(bias + c + 1);
#pragma unroll
        for (int mj = 0; mj < 2; mj++) {
            const int r = rbase + mj * 16;
            float2 v0, v1;
            v0.x = acc[mj][o][0] * xsv[mj][0] * ws0 + bi0;
            v0.y = acc[mj][o][1] * xsv[mj][0] * ws1 + bi1;
            v1.x = acc[mj][o][2] * xsv[mj][1] * ws0 + bi0;
            v1.y = acc[mj][o][3] * xsv[mj][1] * ws1 + bi1;
            __stcs(reinterpret_cast<float2*>(out + (size_t)r * NDIM + c), v0);
            __stcs(reinterpret_cast<float2*>(out + (size_t)(r + 8) * NDIM + c), v1);
        }
    }
}

// ============================================================================
// Host
// ============================================================================
extern "C" void kernel_launch(void* const* d_in, const int* in_sizes, int n_in,
                              void* d_out, int out_size) {
    const float* x    = (const float*)d_in[0];
    const float* w    = (const float*)d_in[1];
    const float* ws   = (const float*)d_in[2];
    const float* bias = (const float*)d_in[3];
    float* out = (float*)d_out;

    void *xq_p = nullptr, *wq_p = nullptr, *xs_p = nullptr;
    cudaGetSymbolAddress(&xq_p, g_xq);
    cudaGetSymbolAddress(&wq_p, g_wq);
    cudaGetSymbolAddress(&xs_p, g_xs);

    cudaFuncSetAttribute(fp8_gemm_kernel,
                         cudaFuncAttributeMaxDynamicSharedMemorySize, SMEM_TOTAL);

    fused_quant_kernel<<<QX_BLOCKS + QW_BLOCKS, 256>>>(
        x, w, (uint8_t*)xq_p, (uint8_t*)wq_p, (float*)xs_p);

    const unsigned nblocks = NBLK * MBLK;   // 8192
    fp8_gemm_kernel<<<nblocks, 128, SMEM_TOTAL>>>((const uint8_t*)xq_p,
                                                  (const uint8_t*)wq_p,
                                                  (const float*)xs_p, ws, bias, out);
}